// round 1
// baseline (speedup 1.0000x reference)
#include <cuda_runtime.h>
#include <math.h>

#define SEQN  4096
#define BATCH 4
#define DIM   1024
#define NH    16
#define DHD   64
#define NL    32
#define WW    8
#define EE    4
#define BAND  16
#define NG    (SEQN / WW)       // 512
#define MROWS (BATCH * SEQN)    // 16384
#define NSPLIT 8
#define CSIZE (BATCH * NH * NL * DHD)  // 131072

// ---------------- device scratch (static globals; no cudaMalloc allowed) ---
__device__ float g_Q  [BATCH * NH * SEQN * DHD];   // (b,h,s,d)
__device__ float g_K  [BATCH * NH * SEQN * DHD];
__device__ float g_V  [BATCH * NH * SEQN * DHD];
__device__ float g_tmp[BATCH * SEQN * DIM];        // raw K/V GEMM output
__device__ float g_D  [BATCH * SEQN * NH * NL];    // raw head scores (b,s,512)
__device__ float g_P  [BATCH * NH * NL * SEQN];    // transposed+softmaxed (b,col,s)
__device__ float g_KcP[NSPLIT * CSIZE];            // split-K partials
__device__ float g_VcP[NSPLIT * CSIZE];
__device__ float g_Kc [CSIZE];                     // (b,h,l,d) LN'd
__device__ float g_Vc [CSIZE];
__device__ float g_C  [BATCH * SEQN * DIM];        // attention output (b,s,DIM)

// ---------------- SGEMM: C = A(16384xK=1024) @ W(1024xN) + bias -----------
// IN_MODE:  0 -> A row r contiguous at r*DIM
//           1 -> A is query (SEQ,B,DIM); row r=(b,s) at (s*B+b)*DIM
// OUT_MODE: 0 -> out[r*N+c]
//           1 -> Q head-split: out[((b*NH+h)*SEQN+s)*DHD+dh], scaled
//           2 -> final out[(s*B+b)*DIM+c]
template <int IN_MODE, int OUT_MODE>
__global__ __launch_bounds__(256) void sgemm_kernel(
    const float* __restrict__ A, const float* __restrict__ Wt,
    const float* __restrict__ bias, float* __restrict__ out,
    int N, float scale)
{
    constexpr int BM = 128, BN = 128, BK = 8;
    __shared__ float As[2][BK][BM];
    __shared__ float Bs[2][BK][BN];

    const int tid = threadIdx.x;
    const int bm = blockIdx.y * BM;
    const int bn = blockIdx.x * BN;

    const int a_row = tid >> 1;
    const int a_col = (tid & 1) << 2;
    size_t a_base;
    {
        int r = bm + a_row;
        if (IN_MODE == 0) {
            a_base = (size_t)r * DIM;
        } else {
            int bb = r >> 12, ss = r & (SEQN - 1);
            a_base = ((size_t)ss * BATCH + bb) * DIM;
        }
    }
    const int b_row = tid >> 5;
    const int b_col = (tid & 31) << 2;
    const size_t b_base = (size_t)b_row * N + bn + b_col;

    float4 aR = *(const float4*)(A + a_base + a_col);
    float4 bR = *(const float4*)(Wt + b_base);
    As[0][a_col + 0][a_row] = aR.x;
    As[0][a_col + 1][a_row] = aR.y;
    As[0][a_col + 2][a_row] = aR.z;
    As[0][a_col + 3][a_row] = aR.w;
    *(float4*)&Bs[0][b_row][b_col] = bR;
    __syncthreads();

    const int tx = tid & 15, ty = tid >> 4;
    float acc[8][8];
#pragma unroll
    for (int i = 0; i < 8; i++)
#pragma unroll
        for (int j = 0; j < 8; j++) acc[i][j] = 0.f;

    int stage = 0;
    constexpr int NIT = DIM / BK;  // 128
#pragma unroll 1
    for (int it = 0; it < NIT; it++) {
        if (it + 1 < NIT) {
            int k0 = (it + 1) * BK;
            aR = *(const float4*)(A + a_base + k0 + a_col);
            bR = *(const float4*)(Wt + (size_t)k0 * N + b_base);
        }
#pragma unroll
        for (int kk = 0; kk < BK; kk++) {
            float af[8], bf[8];
            *(float4*)(af)     = *(float4*)&As[stage][kk][ty * 8];
            *(float4*)(af + 4) = *(float4*)&As[stage][kk][ty * 8 + 4];
            *(float4*)(bf)     = *(float4*)&Bs[stage][kk][tx * 8];
            *(float4*)(bf + 4) = *(float4*)&Bs[stage][kk][tx * 8 + 4];
#pragma unroll
            for (int i = 0; i < 8; i++)
#pragma unroll
                for (int j = 0; j < 8; j++) acc[i][j] += af[i] * bf[j];
        }
        if (it + 1 < NIT) {
            stage ^= 1;
            As[stage][a_col + 0][a_row] = aR.x;
            As[stage][a_col + 1][a_row] = aR.y;
            As[stage][a_col + 2][a_row] = aR.z;
            As[stage][a_col + 3][a_row] = aR.w;
            *(float4*)&Bs[stage][b_row][b_col] = bR;
            __syncthreads();
        }
    }

#pragma unroll
    for (int i = 0; i < 8; i++) {
        int r = bm + ty * 8 + i;
        int bb = r >> 12, ss = r & (SEQN - 1);
#pragma unroll
        for (int j = 0; j < 8; j++) {
            int c = bn + tx * 8 + j;
            float v = (acc[i][j] + bias[c]) * scale;
            if (OUT_MODE == 0) {
                out[(size_t)r * N + c] = v;
            } else if (OUT_MODE == 1) {
                int hh = c >> 6, dd = c & 63;
                out[((size_t)(bb * NH + hh) * SEQN + ss) * DHD + dd] = v;
            } else {
                out[((size_t)ss * BATCH + bb) * DIM + c] = v;
            }
        }
    }
}

// ---------------- LayerNorm over DIM, scatter to head-split layout --------
__global__ __launch_bounds__(256) void ln_split_kernel(
    const float* __restrict__ X, const float* __restrict__ gamma,
    const float* __restrict__ beta, float* __restrict__ out)
{
    __shared__ float shs[8], shq[8];
    int r = blockIdx.x;
    int tid = threadIdx.x;
    const float4 v = ((const float4*)(X + (size_t)r * DIM))[tid];
    float s = v.x + v.y + v.z + v.w;
    float q = v.x * v.x + v.y * v.y + v.z * v.z + v.w * v.w;
    int lane = tid & 31, wid = tid >> 5;
#pragma unroll
    for (int o = 16; o; o >>= 1) {
        s += __shfl_xor_sync(~0u, s, o);
        q += __shfl_xor_sync(~0u, q, o);
    }
    if (lane == 0) { shs[wid] = s; shq[wid] = q; }
    __syncthreads();
    if (tid == 0) {
        float ts = 0, tq = 0;
        for (int i = 0; i < 8; i++) { ts += shs[i]; tq += shq[i]; }
        shs[0] = ts; shq[0] = tq;
    }
    __syncthreads();
    float mean = shs[0] * (1.f / DIM);
    float var  = shq[0] * (1.f / DIM) - mean * mean;
    float rstd = rsqrtf(var + 1e-5f);
    int c = tid * 4;
    float4 g4 = ((const float4*)gamma)[tid];
    float4 b4 = ((const float4*)beta)[tid];
    float4 o;
    o.x = (v.x - mean) * rstd * g4.x + b4.x;
    o.y = (v.y - mean) * rstd * g4.y + b4.y;
    o.z = (v.z - mean) * rstd * g4.z + b4.z;
    o.w = (v.w - mean) * rstd * g4.w + b4.w;
    int b = r >> 12, sq = r & (SEQN - 1);
    int h = c >> 6, dh = c & 63;
    *(float4*)(out + ((size_t)(b * NH + h) * SEQN + sq) * DHD + dh) = o;
}

// ---------------- transpose (b, s, 512) -> (b, 512, s) --------------------
__global__ void transpose_kernel(const float* __restrict__ D, float* __restrict__ P)
{
    __shared__ float t[32][33];
    int b = blockIdx.z;
    int c0 = blockIdx.x * 32, s0 = blockIdx.y * 32;
    int x = threadIdx.x, y = threadIdx.y;  // (32,8)
    const float* Db = D + (size_t)b * SEQN * (NH * NL);
    float* Pb = P + (size_t)b * (NH * NL) * SEQN;
#pragma unroll
    for (int i = 0; i < 32; i += 8)
        t[y + i][x] = Db[(size_t)(s0 + y + i) * (NH * NL) + c0 + x];
    __syncthreads();
#pragma unroll
    for (int i = 0; i < 32; i += 8)
        Pb[(size_t)(c0 + y + i) * SEQN + s0 + x] = t[x][y + i];
}

// ---------------- row softmax over 4096 (sequence axis of head_scores) ----
__global__ __launch_bounds__(256) void softmax_rows_kernel(float* __restrict__ P)
{
    __shared__ float sh[8];
    size_t base = (size_t)blockIdx.x * SEQN;
    int tid = threadIdx.x;
    int lane = tid & 31, wid = tid >> 5;
    float v[16];
    float m = -1e30f;
#pragma unroll
    for (int i = 0; i < 16; i++) {
        v[i] = P[base + tid + i * 256];
        m = fmaxf(m, v[i]);
    }
#pragma unroll
    for (int o = 16; o; o >>= 1) m = fmaxf(m, __shfl_xor_sync(~0u, m, o));
    if (lane == 0) sh[wid] = m;
    __syncthreads();
    if (tid == 0) {
        float t = sh[0];
        for (int i = 1; i < 8; i++) t = fmaxf(t, sh[i]);
        sh[0] = t;
    }
    __syncthreads();
    float M = sh[0];
    __syncthreads();
    float s = 0.f;
#pragma unroll
    for (int i = 0; i < 16; i++) { v[i] = __expf(v[i] - M); s += v[i]; }
#pragma unroll
    for (int o = 16; o; o >>= 1) s += __shfl_xor_sync(~0u, s, o);
    if (lane == 0) sh[wid] = s;
    __syncthreads();
    if (tid == 0) {
        float t = 0;
        for (int i = 0; i < 8; i++) t += sh[i];
        sh[0] = t;
    }
    __syncthreads();
    float inv = 1.f / sh[0];
#pragma unroll
    for (int i = 0; i < 16; i++) P[base + tid + i * 256] = v[i] * inv;
}

// ---------------- Kc/Vc = hs @ K / hs @ V  (split-K over s, partials) -----
__global__ __launch_bounds__(256) void compress_partial_kernel(
    const float* __restrict__ P, const float* __restrict__ K,
    const float* __restrict__ V, float* __restrict__ partK,
    float* __restrict__ partV)
{
    __shared__ float Ps[NL][33];
    __shared__ float Ks[32][DHD];
    __shared__ float Vs[32][DHD];
    int bh = blockIdx.x, sp = blockIdx.y;
    int b = bh >> 4, h = bh & 15;
    int tid = threadIdx.x;
    int l = tid >> 3, qd = (tid & 7) * 8;
    float accK[8] = {0, 0, 0, 0, 0, 0, 0, 0};
    float accV[8] = {0, 0, 0, 0, 0, 0, 0, 0};
    const float* Pb = P + (size_t)(b * (NH * NL) + h * NL) * SEQN;
    const float* Kb = K + (size_t)bh * SEQN * DHD;
    const float* Vb = V + (size_t)bh * SEQN * DHD;
    const int schunk = SEQN / NSPLIT;  // 512
    for (int sc = 0; sc < schunk; sc += 32) {
        int s0 = sp * schunk + sc;
        {
            int pl = tid >> 3, ps = (tid & 7) * 4;
            float4 p4 = *(const float4*)(Pb + (size_t)pl * SEQN + s0 + ps);
            Ps[pl][ps] = p4.x; Ps[pl][ps + 1] = p4.y;
            Ps[pl][ps + 2] = p4.z; Ps[pl][ps + 3] = p4.w;
        }
        {
            int ks = tid >> 3, kd = (tid & 7) * 8;
            const float* kp = Kb + (size_t)(s0 + ks) * DHD + kd;
            *(float4*)&Ks[ks][kd]     = *(const float4*)kp;
            *(float4*)&Ks[ks][kd + 4] = *(const float4*)(kp + 4);
            const float* vp = Vb + (size_t)(s0 + ks) * DHD + kd;
            *(float4*)&Vs[ks][kd]     = *(const float4*)vp;
            *(float4*)&Vs[ks][kd + 4] = *(const float4*)(vp + 4);
        }
        __syncthreads();
#pragma unroll 8
        for (int si = 0; si < 32; si++) {
            float p = Ps[l][si];
            float kf[8], vf[8];
            *(float4*)kf       = *(float4*)&Ks[si][qd];
            *(float4*)(kf + 4) = *(float4*)&Ks[si][qd + 4];
            *(float4*)vf       = *(float4*)&Vs[si][qd];
            *(float4*)(vf + 4) = *(float4*)&Vs[si][qd + 4];
#pragma unroll
            for (int j = 0; j < 8; j++) {
                accK[j] += p * kf[j];
                accV[j] += p * vf[j];
            }
        }
        __syncthreads();
    }
    size_t ob = (size_t)sp * CSIZE + ((size_t)bh * NL + l) * DHD + qd;
    *(float4*)(partK + ob)     = make_float4(accK[0], accK[1], accK[2], accK[3]);
    *(float4*)(partK + ob + 4) = make_float4(accK[4], accK[5], accK[6], accK[7]);
    *(float4*)(partV + ob)     = make_float4(accV[0], accV[1], accV[2], accV[3]);
    *(float4*)(partV + ob + 4) = make_float4(accV[4], accV[5], accV[6], accV[7]);
}

// ---------------- reduce partials + LayerNorm over DIM for Kc/Vc ----------
__global__ __launch_bounds__(256) void compress_ln_kernel(
    const float* __restrict__ partK, const float* __restrict__ partV,
    const float* __restrict__ gamma, const float* __restrict__ beta,
    float* __restrict__ outK, float* __restrict__ outV)
{
    __shared__ float shs[8], shq[8];
    int bl = blockIdx.x;
    int b = bl >> 5, l = bl & 31;
    const float* part = blockIdx.y ? partV : partK;
    float* out = blockIdx.y ? outV : outK;
    int tid = threadIdx.x;
    int c = tid * 4;
    int h = c >> 6, dh = c & 63;
    size_t base = ((size_t)(b * NH + h) * NL + l) * DHD + dh;
    float4 acc = make_float4(0, 0, 0, 0);
#pragma unroll
    for (int sp = 0; sp < NSPLIT; sp++) {
        float4 p = *(const float4*)(part + (size_t)sp * CSIZE + base);
        acc.x += p.x; acc.y += p.y; acc.z += p.z; acc.w += p.w;
    }
    float s = acc.x + acc.y + acc.z + acc.w;
    float q = acc.x * acc.x + acc.y * acc.y + acc.z * acc.z + acc.w * acc.w;
    int lane = tid & 31, wid = tid >> 5;
#pragma unroll
    for (int o = 16; o; o >>= 1) {
        s += __shfl_xor_sync(~0u, s, o);
        q += __shfl_xor_sync(~0u, q, o);
    }
    if (lane == 0) { shs[wid] = s; shq[wid] = q; }
    __syncthreads();
    if (tid == 0) {
        float ts = 0, tq = 0;
        for (int i = 0; i < 8; i++) { ts += shs[i]; tq += shq[i]; }
        shs[0] = ts; shq[0] = tq;
    }
    __syncthreads();
    float mean = shs[0] * (1.f / DIM);
    float var  = shq[0] * (1.f / DIM) - mean * mean;
    float rstd = rsqrtf(var + 1e-5f);
    float4 g4 = ((const float4*)gamma)[tid];
    float4 b4 = ((const float4*)beta)[tid];
    float4 o;
    o.x = (acc.x - mean) * rstd * g4.x + b4.x;
    o.y = (acc.y - mean) * rstd * g4.y + b4.y;
    o.z = (acc.z - mean) * rstd * g4.z + b4.z;
    o.w = (acc.w - mean) * rstd * g4.w + b4.w;
    *(float4*)(out + base) = o;
}

// ---------------- fused attention: compressed(32) + window(16) ------------
__global__ __launch_bounds__(256) void attn_kernel(
    const float* __restrict__ Q, const float* __restrict__ K,
    const float* __restrict__ V, const float* __restrict__ Kc,
    const float* __restrict__ Vc, float* __restrict__ C)
{
    __shared__ float Kcs[NL][DHD + 1];
    __shared__ float Vcs[NL][DHD + 1];
    __shared__ float Kws[BAND][DHD + 1];
    __shared__ float Vws[BAND][DHD + 1];
    __shared__ float Qs[WW][DHD + 1];
    __shared__ float probs[WW][NL + BAND];

    int g = blockIdx.x, h = blockIdx.y, b = blockIdx.z;
    int bh = b * NH + h;
    int tid = threadIdx.x;

    {   // Kc/Vc tiles: 32x64 each
        int l = tid >> 3, d0 = (tid & 7) * 8;
        size_t src = ((size_t)bh * NL + l) * DHD + d0;
        float tk[8], tv[8];
        *(float4*)tk       = *(const float4*)(Kc + src);
        *(float4*)(tk + 4) = *(const float4*)(Kc + src + 4);
        *(float4*)tv       = *(const float4*)(Vc + src);
        *(float4*)(tv + 4) = *(const float4*)(Vc + src + 4);
#pragma unroll
        for (int i = 0; i < 8; i++) { Kcs[l][d0 + i] = tk[i]; Vcs[l][d0 + i] = tv[i]; }
    }
    {   // window K/V tiles: 16x64, zero-filled when out of range
        int k = tid >> 4, d = (tid & 15) * 4;
        int sk = g * WW - EE + k;
        float4 kv = make_float4(0, 0, 0, 0), vv = make_float4(0, 0, 0, 0);
        if (sk >= 0 && sk < SEQN) {
            size_t src = ((size_t)bh * SEQN + sk) * DHD + d;
            kv = *(const float4*)(K + src);
            vv = *(const float4*)(V + src);
        }
        Kws[k][d] = kv.x; Kws[k][d + 1] = kv.y; Kws[k][d + 2] = kv.z; Kws[k][d + 3] = kv.w;
        Vws[k][d] = vv.x; Vws[k][d + 1] = vv.y; Vws[k][d + 2] = vv.z; Vws[k][d + 3] = vv.w;
    }
    if (tid < 128) {  // Q tile: 8x64
        int w = tid >> 4, d = (tid & 15) * 4;
        float4 qv = *(const float4*)(Q + ((size_t)bh * SEQN + g * WW + w) * DHD + d);
        Qs[w][d] = qv.x; Qs[w][d + 1] = qv.y; Qs[w][d + 2] = qv.z; Qs[w][d + 3] = qv.w;
    }
    __syncthreads();

    int warp = tid >> 5, lane = tid & 31;
    float sc = 0.f, sw = 0.f;
    int k = lane & 15;
#pragma unroll
    for (int d = 0; d < DHD; d++) {
        float qd = Qs[warp][d];
        sc += qd * Kcs[lane][d];
        sw += qd * Kws[k][d];
    }
    int sk = g * WW - EE + k;
    bool kvalid = (lane < BAND) && (sk >= 0) && (sk < SEQN);
    float m = fmaxf(sc, kvalid ? sw : -1e30f);
#pragma unroll
    for (int o = 16; o; o >>= 1) m = fmaxf(m, __shfl_xor_sync(~0u, m, o));
    float e0 = __expf(sc - m);
    float e1 = kvalid ? __expf(sw - m) : 0.f;
    float t = e0 + e1;
#pragma unroll
    for (int o = 16; o; o >>= 1) t += __shfl_xor_sync(~0u, t, o);
    float inv = 1.f / t;
    probs[warp][lane] = e0 * inv;
    if (lane < BAND) probs[warp][NL + lane] = e1 * inv;
    __syncwarp();

    float a0 = 0.f, a1 = 0.f;
#pragma unroll
    for (int j = 0; j < NL; j++) {
        float p = probs[warp][j];
        a0 += p * Vcs[j][lane];
        a1 += p * Vcs[j][lane + 32];
    }
#pragma unroll
    for (int kk = 0; kk < BAND; kk++) {
        float p = probs[warp][NL + kk];
        a0 += p * Vws[kk][lane];
        a1 += p * Vws[kk][lane + 32];
    }
    int s = g * WW + warp;
    size_t off = ((size_t)(b * SEQN) + s) * DIM + h * DHD;
    C[off + lane] = a0;
    C[off + 32 + lane] = a1;
}

// ---------------------------------------------------------------------------
extern "C" void kernel_launch(void* const* d_in, const int* in_sizes, int n_in,
                              void* d_out, int out_size)
{
    (void)in_sizes; (void)n_in; (void)out_size;
    const float* query = (const float*)d_in[0];
    const float* Wq = (const float*)d_in[1];
    const float* bq = (const float*)d_in[2];
    const float* Wk = (const float*)d_in[3];
    const float* bk = (const float*)d_in[4];
    const float* Wv = (const float*)d_in[5];
    const float* bv = (const float*)d_in[6];
    const float* Wo = (const float*)d_in[7];
    const float* bo = (const float*)d_in[8];
    const float* gl = (const float*)d_in[9];
    const float* bl = (const float*)d_in[10];
    const float* gs = (const float*)d_in[11];
    const float* bs = (const float*)d_in[12];
    const float* Wd = (const float*)d_in[13];
    const float* bd = (const float*)d_in[14];
    float* out = (float*)d_out;

    float *pQ, *pK, *pV, *pTmp, *pD, *pP, *pKcP, *pVcP, *pKc, *pVc, *pC;
    cudaGetSymbolAddress((void**)&pQ, g_Q);
    cudaGetSymbolAddress((void**)&pK, g_K);
    cudaGetSymbolAddress((void**)&pV, g_V);
    cudaGetSymbolAddress((void**)&pTmp, g_tmp);
    cudaGetSymbolAddress((void**)&pD, g_D);
    cudaGetSymbolAddress((void**)&pP, g_P);
    cudaGetSymbolAddress((void**)&pKcP, g_KcP);
    cudaGetSymbolAddress((void**)&pVcP, g_VcP);
    cudaGetSymbolAddress((void**)&pKc, g_Kc);
    cudaGetSymbolAddress((void**)&pVc, g_Vc);
    cudaGetSymbolAddress((void**)&pC, g_C);

    dim3 gQKV(DIM / 128, MROWS / 128);       // 8 x 128
    dim3 gD((NH * NL) / 128, MROWS / 128);   // 4 x 128

    // Q = split(X@Wq + bq) / 8
    sgemm_kernel<1, 1><<<gQKV, 256>>>(query, Wq, bq, pQ, DIM, 0.125f);
    // K = split(LN(X@Wk + bk))
    sgemm_kernel<1, 0><<<gQKV, 256>>>(query, Wk, bk, pTmp, DIM, 1.f);
    ln_split_kernel<<<MROWS, 256>>>(pTmp, gl, bl, pK);
    // V = split(LN(X@Wv + bv))
    sgemm_kernel<1, 0><<<gQKV, 256>>>(query, Wv, bv, pTmp, DIM, 1.f);
    ln_split_kernel<<<MROWS, 256>>>(pTmp, gl, bl, pV);
    // head scores D = X@Wd + bd, then softmax over sequence axis
    sgemm_kernel<1, 0><<<gD, 256>>>(query, Wd, bd, pD, NH * NL, 1.f);
    transpose_kernel<<<dim3((NH * NL) / 32, SEQN / 32, BATCH), dim3(32, 8)>>>(pD, pP);
    softmax_rows_kernel<<<BATCH * NH * NL, 256>>>(pP);
    // Kc/Vc = hs @ K / hs @ V (split-K), then LN over DIM
    compress_partial_kernel<<<dim3(BATCH * NH, NSPLIT), 256>>>(pP, pK, pV, pKcP, pVcP);
    compress_ln_kernel<<<dim3(BATCH * NL, 2), 256>>>(pKcP, pVcP, gs, bs, pKc, pVc);
    // fused compressed+window attention -> C (b,s,DIM)
    attn_kernel<<<dim3(NG, NH, BATCH), 256>>>(pQ, pK, pV, pKc, pVc, pC);
    // out = C @ Wo + bo, permuted to (s,b,DIM)
    sgemm_kernel<0, 2><<<gQKV, 256>>>(pC, Wo, bo, out, DIM, 1.f);
}